// round 17
// baseline (speedup 1.0000x reference)
#include <cuda_runtime.h>
#include <cuda_fp16.h>
#include <math.h>
#include <stdint.h>

#define BB 256
#define HH 512
#define H4 2048
#define LEN 48
#define LOOKN 10
#define K2H 1024
#define STARTI 48
#define LABW 58
#define NBLK 296
#define NTHR 256
#define NSUB 8
#define SUBCNT 37
#define PADU 36
#define ABUFS (4*64*PADU)
#define SMEMB (2*ABUFS*4)

constexpr size_t O_WISEQ = 0;
constexpr size_t O_MID2  = O_WISEQ + (size_t)BB*LEN*HH;
constexpr size_t O_Y     = O_MID2  + (size_t)BB*LEN*HH;
constexpr size_t O_HT0   = O_Y     + (size_t)BB*LEN*HH;
constexpr size_t O_HT1   = O_HT0   + (size_t)BB*K2H;
constexpr size_t O_HE0   = O_HT1   + (size_t)BB*K2H;
constexpr size_t O_HE1   = O_HE0   + (size_t)BB*K2H;
constexpr size_t O_HM0   = O_HE1   + (size_t)BB*K2H;
constexpr size_t O_HM1   = O_HM0   + (size_t)BB*K2H;
constexpr size_t O_WTWHO = O_HM1   + (size_t)BB*K2H;
constexpr size_t O_LAB   = O_WTWHO + (size_t)BB*K2H;
constexpr size_t O_PARTA = O_LAB   + 1024;               // [BB][16] parity 0
constexpr size_t O_PARTB = O_PARTA + (size_t)BB*16;      // [BB][16] parity 1
constexpr size_t O_BSPI  = O_PARTB + (size_t)BB*16;
constexpr size_t O_BTGI  = O_BSPI  + H4;
constexpr size_t O_BMDI  = O_BTGI  + H4;
constexpr size_t O_WTGCI = O_BMDI  + H4;
constexpr size_t O_INP16 = O_WTGCI + H4;
constexpr size_t O_MID216= O_INP16 + (size_t)BB*LEN*256;
constexpr size_t O_DEC16 = O_MID216+ (size_t)BB*LEN*256;
constexpr size_t O_XE16A = O_DEC16 + (size_t)BB*256;     // parity 0
constexpr size_t O_XE16B = O_XE16A + (size_t)BB*256;     // parity 1
constexpr size_t O_TU16  = O_XE16B + (size_t)BB*256;
constexpr size_t O_HT16A = O_TU16  + (size_t)BB*256;
constexpr size_t O_HT16B = O_HT16A + (size_t)BB*512;
constexpr size_t O_HE16A = O_HT16B + (size_t)BB*512;
constexpr size_t O_HE16B = O_HE16A + (size_t)BB*512;
constexpr size_t O_HM16A = O_HE16B + (size_t)BB*512;
constexpr size_t O_HM16B = O_HM16A + (size_t)BB*512;
constexpr size_t O_WI16  = O_HM16B + (size_t)BB*512;
constexpr size_t O_WE16  = O_WI16  + (size_t)512*256;
constexpr size_t O_VD16  = O_WE16  + (size_t)512*512;
constexpr size_t O_WX16  = O_VD16  + (size_t)512*256;
constexpr size_t O_WTWH16= O_WX16  + (size_t)512*256;
constexpr size_t O_SPIH  = O_WTWH16+ (size_t)1024*512;
constexpr size_t O_SPHH  = O_SPIH  + (size_t)H4*256;
constexpr size_t O_TGX   = O_SPHH  + (size_t)H4*256;
constexpr size_t O_TGHH  = O_TGX   + (size_t)H4*256;
constexpr size_t O_MDIH  = O_TGHH  + (size_t)H4*256;
constexpr size_t O_MDHH  = O_MDIH  + (size_t)H4*256;
constexpr size_t O_PBUF0 = O_MDHH  + (size_t)H4*256;     // fp32 P parity 0 [BB][H4]
constexpr size_t O_PBUF1 = O_PBUF0 + (size_t)BB*H4;      // fp32 P parity 1
constexpr size_t G_TOTAL = O_PBUF1 + (size_t)BB*H4;

__device__ float g_buf[G_TOTAL];
__device__ __align__(128) unsigned g_arr[NSUB * 32];
__device__ unsigned g_master;
__device__ unsigned g_rel;
__device__ __align__(128) unsigned g_flagA[4 * 32];
__device__ __align__(128) unsigned g_flagT[4 * 32];

__device__ __forceinline__ void gsync(unsigned ph)
{
    __syncthreads();
    if (threadIdx.x == 0) {
        __threadfence();
        const unsigned sub = blockIdx.x & (NSUB - 1);
        const unsigned v = atomicAdd(&g_arr[sub * 32], 1u) + 1u;
        if (v == ph * (unsigned)SUBCNT) {
            const unsigned m = atomicAdd(&g_master, 1u) + 1u;
            if (m == ph * (unsigned)NSUB) atomicExch(&g_rel, ph);
        }
        while (*(volatile unsigned*)&g_rel < ph) { __nanosleep(32); }
        __threadfence();
    }
    __syncthreads();
}

__device__ __forceinline__ uint32_t s2u(const void* p)
{ uint32_t a; asm("{ .reg .u64 t; cvta.to.shared.u64 t, %1; cvt.u32.u64 %0, t; }" : "=r"(a) : "l"(p)); return a; }

__device__ __forceinline__ void mma_f16(float* d,
    uint32_t a0, uint32_t a1, uint32_t a2, uint32_t a3, uint32_t b0, uint32_t b1)
{
    asm volatile(
        "mma.sync.aligned.m16n8k16.row.col.f32.f16.f16.f32 "
        "{%0,%1,%2,%3},{%4,%5,%6,%7},{%8,%9},{%0,%1,%2,%3};"
        : "+f"(d[0]), "+f"(d[1]), "+f"(d[2]), "+f"(d[3])
        : "r"(a0), "r"(a1), "r"(a2), "r"(a3), "r"(b0), "r"(b1));
}

struct Params {
    const float *inp;
    const float *Wi_b, *Vd_b, *Wx_b, *V_w, *V_b, *reg_w, *reg_b;
    float* out; float* gb;
};

__device__ __forceinline__ void cpAB(uint32_t sb, int buf, int srow, int sq,
    const uint16_t* Ap, int Alda, int m0,
    const uint16_t* Wp, int Wld, int n0, int ko)
{
    const uint16_t* ar = Ap + (size_t)(m0 + srow) * Alda + ko + sq * 16;
    const uint16_t* wr = Wp + (size_t)(n0 + srow) * Wld + ko + sq * 16;
    const uint32_t da = sb + ((buf * 64 + srow) * PADU + sq * 8) * 4;
    const uint32_t db = da + ABUFS * 4;
    asm volatile(
        "cp.async.ca.shared.global [%0],[%4],16;\n\t"
        "cp.async.ca.shared.global [%1],[%5],16;\n\t"
        "cp.async.ca.shared.global [%2],[%6],16;\n\t"
        "cp.async.ca.shared.global [%3],[%7],16;\n\t"
        "cp.async.commit_group;"
        :: "r"(da), "r"(da+16), "r"(db), "r"(db+16),
           "l"(ar), "l"(ar+8), "l"(wr), "l"(wr+8) : "memory");
}

// modes: 0 fp32 store(+bias); 1 tanh->fp16(+add1+add2); 2 fused LSTM(+opt bias/add1/r1);
//        3 exp: xe16 + partial sums
__device__ void gemm16(
    const uint16_t* A1, int lda1, const uint16_t* W1, int K1,
    const uint16_t* A2, int lda2, const uint16_t* W2, int K2,
    const float* bias, const float* add1, int ld1, const float* add2, int ld2,
    const float* r1u, const float* r1v,
    const float* cin, const float* invp,
    const float* xsrc, int xld,
    float* out32, uint16_t* out16,
    float* hout32, uint16_t* hout16, int hstride,
    int M, int N, int mode,
    uint32_t* dsm, int vbid, int vgrid,
    unsigned* sigf, const unsigned* waitf, unsigned wtarget)
{
    const int tid = threadIdx.x, wid = tid >> 5, lane = tid & 31;
    const int g = lane >> 2, c4 = lane & 3;
    const int wm = (wid >> 1) << 4, wn = (wid & 1) << 5;
    const int srow = tid >> 2, sq = tid & 3;
    const int NC = (K1 + K2) >> 6, k1c = K1 >> 6;
    const int nct = N >> 6, ntiles = (M >> 6) * nct;
    const uint32_t sb = s2u(dsm);
    const uint32_t* Bb = dsm + ABUFS;

    for (int t = vbid; t < ntiles; t += vgrid) {
        const int m0 = (t / nct) << 6, n0 = (t % nct) << 6;

        if (waitf) {
            if (tid == 0) {
                while (*(volatile const unsigned*)&waitf[(m0 >> 6) * 32] < wtarget)
                    __nanosleep(32);
            }
            __syncthreads();
            __threadfence();
        }

        float sc2[2] = {1.f, 1.f};
        if (invp) {
#pragma unroll
            for (int r = 0; r < 2; r++) {
                const int row = m0 + wm + (r << 3) + g;
                float s = 0.f;
#pragma unroll
                for (int q = 0; q < 16; q++) s += invp[row * 16 + q];
                sc2[r] = 1.f / s;
            }
        }

        float acc[4][4];
#pragma unroll
        for (int j = 0; j < 4; j++)
#pragma unroll
            for (int q = 0; q < 4; q++) acc[j][q] = 0.f;

#pragma unroll
        for (int s = 0; s < 3; s++) {
            if (s < NC) {
                const int kb = s << 6;
                if (kb < K1) cpAB(sb, s, srow, sq, A1, lda1, m0, W1, K1, n0, kb);
                else         cpAB(sb, s, srow, sq, A2, lda2, m0, W2, K2, n0, kb - K1);
            }
        }

        for (int c = 0; c < NC; c++) {
            const int rem = NC - 1 - c;
            const int pend = rem < 2 ? rem : 2;
            if (pend == 2)      asm volatile("cp.async.wait_group 2;" ::: "memory");
            else if (pend == 1) asm volatile("cp.async.wait_group 1;" ::: "memory");
            else                asm volatile("cp.async.wait_group 0;" ::: "memory");
            __syncthreads();
            const int cn = c + 3;
            if (cn < NC) {
                const int kb = cn << 6;
                if (kb < K1) cpAB(sb, cn & 3, srow, sq, A1, lda1, m0, W1, K1, n0, kb);
                else         cpAB(sb, cn & 3, srow, sq, A2, lda2, m0, W2, K2, n0, kb - K1);
            }
            const int b = c & 3;
#pragma unroll
            for (int ks = 0; ks < 4; ks++) {
                uint32_t af[4], bf[4][2];
                {
                    const uint32_t* ab  = dsm + (b * 64 + wm + g) * PADU + ks * 8;
                    const uint32_t* ab8 = dsm + (b * 64 + wm + g + 8) * PADU + ks * 8;
                    af[0] = ab[c4];   af[1] = ab8[c4];
                    af[2] = ab[c4+4]; af[3] = ab8[c4+4];
                }
#pragma unroll
                for (int nf = 0; nf < 4; nf++) {
                    const int r = wn + (nf << 3) + g;
                    const uint32_t* bb = Bb + (b * 64 + r) * PADU + ks * 8;
                    bf[nf][0] = bb[c4]; bf[nf][1] = bb[c4 + 4];
                }
#pragma unroll
                for (int nf = 0; nf < 4; nf++)
                    mma_f16(acc[nf], af[0], af[1], af[2], af[3], bf[nf][0], bf[nf][1]);
            }
            if (invp && c == k1c - 1) {
#pragma unroll
                for (int nf = 0; nf < 4; nf++) {
                    acc[nf][0] *= sc2[0]; acc[nf][1] *= sc2[0];
                    acc[nf][2] *= sc2[1]; acc[nf][3] *= sc2[1];
                }
            }
        }

        const int mA = m0 + wm + g, mB = mA + 8;
        const int nb0 = n0 + wn;
        if (mode == 0) {
#pragma unroll
            for (int nf = 0; nf < 4; nf++) {
                const int nc = nb0 + (nf << 3) + (c4 << 1);
                float x0 = acc[nf][0], x1 = acc[nf][1];
                float x2 = acc[nf][2], x3 = acc[nf][3];
                if (bias) { x0 += bias[nc]; x1 += bias[nc+1]; x2 += bias[nc]; x3 += bias[nc+1]; }
                *(float2*)(out32 + (size_t)mA * N + nc) = make_float2(x0, x1);
                *(float2*)(out32 + (size_t)mB * N + nc) = make_float2(x2, x3);
            }
        } else if (mode == 1) {
#pragma unroll
            for (int nf = 0; nf < 4; nf++) {
                const int nc = nb0 + (nf << 3) + (c4 << 1);
                float x0 = acc[nf][0], x1 = acc[nf][1];
                float x2 = acc[nf][2], x3 = acc[nf][3];
                x0 += add1[(size_t)mA*ld1+nc]; x1 += add1[(size_t)mA*ld1+nc+1];
                x2 += add1[(size_t)mB*ld1+nc]; x3 += add1[(size_t)mB*ld1+nc+1];
                x0 += add2[(size_t)mA*ld2+nc]; x1 += add2[(size_t)mA*ld2+nc+1];
                x2 += add2[(size_t)mB*ld2+nc]; x3 += add2[(size_t)mB*ld2+nc+1];
                __half2 hA = __floats2half2_rn(tanhf(x0), tanhf(x1));
                __half2 hB = __floats2half2_rn(tanhf(x2), tanhf(x3));
                *(uint32_t*)(out16 + (size_t)mA * N + nc) = *(uint32_t*)&hA;
                *(uint32_t*)(out16 + (size_t)mB * N + nc) = *(uint32_t*)&hB;
            }
        } else if (mode == 3) {
            float sA = 0.f, sB = 0.f;
#pragma unroll
            for (int nf = 0; nf < 4; nf++) {
                const int nc = nb0 + (nf << 3) + (c4 << 1);
                float e0 = expf(acc[nf][0] + bias[nc]);
                float e1 = expf(acc[nf][1] + bias[nc+1]);
                float e2 = expf(acc[nf][2] + bias[nc]);
                float e3 = expf(acc[nf][3] + bias[nc+1]);
                sA += e0 + e1; sB += e2 + e3;
                float2 xa = *(const float2*)(xsrc + (size_t)mA * xld + nc);
                float2 xb = *(const float2*)(xsrc + (size_t)mB * xld + nc);
                __half2 hA = __floats2half2_rn(xa.x * e0, xa.y * e1);
                __half2 hB = __floats2half2_rn(xb.x * e2, xb.y * e3);
                *(uint32_t*)(out16 + (size_t)mA * 512 + nc) = *(uint32_t*)&hA;
                *(uint32_t*)(out16 + (size_t)mB * 512 + nc) = *(uint32_t*)&hB;
            }
            sA += __shfl_xor_sync(0xffffffffu, sA, 1);
            sA += __shfl_xor_sync(0xffffffffu, sA, 2);
            sB += __shfl_xor_sync(0xffffffffu, sB, 1);
            sB += __shfl_xor_sync(0xffffffffu, sB, 2);
            if (c4 == 0) {
                out32[mA * 16 + (nb0 >> 5)] = sA;
                out32[mB * 16 + (nb0 >> 5)] = sB;
            }
        } else {
            const float ra = r1u ? r1u[mA] : 0.f, rb = r1u ? r1u[mB] : 0.f;
#pragma unroll
            for (int nf = 0; nf < 4; nf++) {
                const int nc = nb0 + (nf << 3) + (c4 << 1);
                float v00 = acc[nf][0], v01 = acc[nf][1];
                float v10 = acc[nf][2], v11 = acc[nf][3];
                if (bias) { v00 += bias[nc]; v01 += bias[nc+1]; v10 += bias[nc]; v11 += bias[nc+1]; }
                if (add1) {
                    v00 += add1[(size_t)mA*ld1+nc]; v01 += add1[(size_t)mA*ld1+nc+1];
                    v10 += add1[(size_t)mB*ld1+nc]; v11 += add1[(size_t)mB*ld1+nc+1];
                }
                if (r1u) {
                    v00 += ra * r1v[nc]; v01 += ra * r1v[nc+1];
                    v10 += rb * r1v[nc]; v11 += rb * r1v[nc+1];
                }
                const float t00 = __shfl_xor_sync(0xffffffffu, v00, 1);
                const float t01 = __shfl_xor_sync(0xffffffffu, v01, 1);
                const float t10 = __shfl_xor_sync(0xffffffffu, v10, 1);
                const float t11 = __shfl_xor_sync(0xffffffffu, v11, 1);
                int m; float fi, ff, fg, fo;
                if ((c4 & 1) == 0) { m = mA; fi = v00; ff = v01; fg = t00; fo = t01; }
                else               { m = mB; fi = t10; ff = t11; fg = v10; fo = v11; }
                const int h = ((nb0 + (nf << 3)) >> 2) + (c4 >> 1);
                const float cold = cin[(size_t)m * 1024 + 512 + h];
                const float si = 1.f / (1.f + expf(-fi));
                const float sf = 1.f / (1.f + expf(-ff));
                const float so = 1.f / (1.f + expf(-fo));
                const float c2 = sf * cold + si * tanhf(fg);
                const float hn = so * tanhf(c2);
                out32[(size_t)m * 1024 + h] = hn;
                out32[(size_t)m * 1024 + 512 + h] = c2;
                out16[(size_t)m * 1024 + h] = __half_as_ushort(__float2half_rn(hn));
                out16[(size_t)m * 1024 + 512 + h] = __half_as_ushort(__float2half_rn(c2));
                if (hout32) {
                    hout32[(size_t)m * hstride + h] = hn;
                    hout16[(size_t)m * hstride + h] = __half_as_ushort(__float2half_rn(hn));
                }
            }
        }
        if (sigf) {
            __threadfence();
            __syncthreads();
            if (tid == 0) atomicAdd(&sigf[(m0 >> 6) * 32], 1u);
        } else {
            __syncthreads();
        }
    }
}

__global__ __launch_bounds__(NTHR, 2) void mega(Params p)
{
    extern __shared__ uint32_t dsm[];
    __shared__ float ssc[LEN];
    const int tid = threadIdx.x, wid = tid >> 5, lane = tid & 31;
    const int bx = blockIdx.x;

    float* gb = p.gb;
    float* wiseq = gb + O_WISEQ;  float* mid2 = gb + O_MID2;  float* ybuf = gb + O_Y;
    float* ht0 = gb + O_HT0;  float* ht1 = gb + O_HT1;
    float* he0 = gb + O_HE0;  float* hm0 = gb + O_HM0;
    float* he1 = gb + O_HE1;  float* hm1 = gb + O_HM1;
    float* wtwho = gb + O_WTWHO;  float* lab = gb + O_LAB;
    float* partb[2] = {gb + O_PARTA, gb + O_PARTB};
    float* Pb[2] = {gb + O_PBUF0, gb + O_PBUF1};
    float* bspi = gb + O_BSPI;  float* btgi = gb + O_BTGI;
    float* bmdi = gb + O_BMDI;  float* wtgci = gb + O_WTGCI;
    uint16_t* INP16 = (uint16_t*)(gb + O_INP16);
    uint16_t* MID216 = (uint16_t*)(gb + O_MID216);
    uint16_t* DEC16 = (uint16_t*)(gb + O_DEC16);
    uint16_t* XEb[2] = {(uint16_t*)(gb + O_XE16A), (uint16_t*)(gb + O_XE16B)};
    uint16_t* TU16 = (uint16_t*)(gb + O_TU16);
    uint16_t* HT16[2] = {(uint16_t*)(gb + O_HT16A), (uint16_t*)(gb + O_HT16B)};
    uint16_t* HE16[2] = {(uint16_t*)(gb + O_HE16A), (uint16_t*)(gb + O_HE16B)};
    uint16_t* HM16[2] = {(uint16_t*)(gb + O_HM16A), (uint16_t*)(gb + O_HM16B)};
    const uint16_t* WI16 = (const uint16_t*)(gb + O_WI16);
    const uint16_t* WE16 = (const uint16_t*)(gb + O_WE16);
    const uint16_t* VD16 = (const uint16_t*)(gb + O_VD16);
    const uint16_t* WX16 = (const uint16_t*)(gb + O_WX16);
    const uint16_t* WTWH16 = (const uint16_t*)(gb + O_WTWH16);
    const uint16_t* SPIH = (const uint16_t*)(gb + O_SPIH);
    const uint16_t* SPHH = (const uint16_t*)(gb + O_SPHH);
    const uint16_t* TGX = (const uint16_t*)(gb + O_TGX);
    const uint16_t* TGHH = (const uint16_t*)(gb + O_TGHH);
    const uint16_t* MDIH = (const uint16_t*)(gb + O_MDIH);
    const uint16_t* MDHH = (const uint16_t*)(gb + O_MDHH);

    unsigned ph = 0;
    unsigned fA = 0, fT = 0;

    gemm16(INP16, 512, WI16, 512, nullptr, 0, nullptr, 0, p.Wi_b,
           nullptr, 0, nullptr, 0, nullptr, nullptr, nullptr, nullptr, nullptr, 0,
           wiseq, nullptr, nullptr, nullptr, 0, BB*LEN, HH, 0, dsm, bx, NBLK,
           nullptr, nullptr, 0);
    gsync(++ph);

    for (int k = 0; k < LOOKN; k++) {
        const int kb = k & 1;
        float* htin32  = kb ? ht1 : ht0;
        float* htout32 = kb ? ht0 : ht1;
        uint16_t* htin16  = HT16[kb];
        uint16_t* htout16 = HT16[kb ^ 1];

        // tg gates (fused LSTM)
        gemm16(DEC16, 512, TGX, 512, htin16, 1024, TGHH, 512, btgi,
               nullptr, 0, nullptr, 0, lab, wtgci, htin32, nullptr, nullptr, 0,
               htout32, htout16, nullptr, nullptr, 0, BB, H4, 2, dsm, bx, NBLK,
               nullptr, nullptr, 0);
        gsync(++ph);

        // wtwh || target || zero states + P0 = bias
        if (bx < 64) {
            gemm16(htout16, 1024, WTWH16, K2H, nullptr, 0, nullptr, 0, nullptr,
                   nullptr, 0, nullptr, 0, nullptr, nullptr, nullptr, nullptr, nullptr, 0,
                   wtwho, nullptr, nullptr, nullptr, 0, BB, K2H, 0, dsm, bx, 64,
                   nullptr, nullptr, 0);
        } else if (bx == 64) {
            for (int r = wid; r < BB; r += 8) {
                float s = 0.f;
                for (int h = lane; h < HH; h += 32) s += htout32[(size_t)r * K2H + h] * p.reg_w[h];
#pragma unroll
                for (int o = 16; o; o >>= 1) s += __shfl_xor_sync(0xffffffffu, s, o);
                if (lane == 0) { const float tv = s + p.reg_b[0]; p.out[r * LOOKN + k] = tv; lab[r] = tv; }
            }
        } else {
            const int base = (bx - 65) * NTHR + tid;
            for (int i = base; i < BB * K2H; i += (NBLK - 65) * NTHR) {
                he0[i] = 0.f; hm0[i] = 0.f;
                ((uint32_t*)HE16[0])[i >> 1] = 0u; ((uint32_t*)HM16[0])[i >> 1] = 0u;
            }
            for (int i = base; i < BB * H4; i += (NBLK - 65) * NTHR)
                Pb[0][i] = bspi[i & (H4 - 1)];
        }
        gsync(++ph);

        // prologue: tu(0) -> sc(0) flag-chained (parity-0 buffers)
        fT++;
        if (bx >= 128 && bx < 160) {
            gemm16(HE16[0], 1024, WE16, K2H, nullptr, 0, nullptr, 0, nullptr,
                   wiseq, LEN * HH, wtwho, K2H, nullptr, nullptr, nullptr, nullptr, nullptr, 0,
                   nullptr, TU16, nullptr, nullptr, 0, BB, HH, 1, dsm, bx - 128, 32,
                   g_flagT, nullptr, 0);
        } else if (bx >= 160 && bx < 192) {
            gemm16(TU16, 512, VD16, 512, nullptr, 0, nullptr, 0, p.Vd_b,
                   nullptr, 0, nullptr, 0, nullptr, nullptr, nullptr, nullptr,
                   p.inp, LEN * 512,
                   partb[0], XEb[0], nullptr, nullptr, 0, BB, HH, 3, dsm, bx - 160, 32,
                   nullptr, g_flagT, 8u * fT);
        }
        gsync(++ph);

        for (int l = 0; l < LEN; l++) {
            const int lb = l & 1;
            float* hein32  = lb ? he1 : he0;
            float* heout32 = lb ? he0 : he1;
            float* hmin32  = lb ? hm1 : hm0;
            float* hmout32 = lb ? hm0 : hm1;
            uint16_t* heout16 = HE16[lb ^ 1];
            uint16_t* hmin16 = HM16[lb], *hmout16 = HM16[lb ^ 1];

            // single merged phase, flag-chained inside
            fA++;
            if (l < LEN - 1) fT++;

            if (bx < 128) {
                // sp_xe(l): fused LSTM, signals flagA per tile
                gemm16(XEb[lb], 512, SPIH, 512, nullptr, 0, nullptr, 0,
                       nullptr, Pb[lb], H4, nullptr, 0,
                       nullptr, nullptr, hein32, partb[lb], nullptr, 0,
                       heout32, heout16, nullptr, nullptr, 0, BB, H4, 2, dsm, bx, 128,
                       g_flagA, nullptr, 0);
            } else if (bx < 264) {
                // mid(l) then sp_hh(l+1), both wait flagA
                gemm16(heout16, 1024, MDIH, 512, hmin16, 1024, MDHH, 512, bmdi,
                       nullptr, 0, nullptr, 0, nullptr, nullptr, hmin32, nullptr, nullptr, 0,
                       hmout32, hmout16, mid2 + (size_t)l * HH, MID216 + (size_t)l * HH, LEN * HH,
                       BB, H4, 2, dsm, bx - 128, 136, nullptr, g_flagA, 32u * fA);
                if (l < LEN - 1) {
                    gemm16(heout16, 1024, SPHH, 512, nullptr, 0, nullptr, 0, bspi,
                           nullptr, 0, nullptr, 0, nullptr, nullptr, nullptr, nullptr, nullptr, 0,
                           Pb[lb ^ 1], nullptr, nullptr, nullptr, 0, BB, H4, 0, dsm, bx - 128, 136,
                           nullptr, g_flagA, 32u * fA);
                }
            } else {
                // tu(l+1) -> sc(l+1)
                if (l < LEN - 1) {
                    gemm16(heout16, 1024, WE16, K2H, nullptr, 0, nullptr, 0, nullptr,
                           wiseq + (size_t)(l + 1) * HH, LEN * HH, wtwho, K2H,
                           nullptr, nullptr, nullptr, nullptr, nullptr, 0,
                           nullptr, TU16, nullptr, nullptr, 0, BB, HH, 1, dsm, bx - 264, 32,
                           g_flagT, g_flagA, 32u * fA);
                    gemm16(TU16, 512, VD16, 512, nullptr, 0, nullptr, 0, p.Vd_b,
                           nullptr, 0, nullptr, 0, nullptr, nullptr, nullptr, nullptr,
                           p.inp + (size_t)(l + 1) * 512, LEN * 512,
                           partb[lb ^ 1], XEb[lb ^ 1], nullptr, nullptr, 0, BB, HH, 3, dsm, bx - 264, 32,
                           nullptr, g_flagT, 8u * fT);
                }
            }
            gsync(++ph);
        }

        gemm16(MID216, 512, WX16, 512, nullptr, 0, nullptr, 0, p.Wx_b,
               nullptr, 0, nullptr, 0, nullptr, nullptr, nullptr, nullptr, nullptr, 0,
               ybuf, nullptr, nullptr, nullptr, 0, BB * LEN, HH, 0, dsm, bx, NBLK,
               nullptr, nullptr, 0);
        gsync(++ph);

        if (bx < BB) {
            const int b = bx;
            for (int l = wid; l < LEN; l += 8) {
                const float* yr = ybuf + ((size_t)b * LEN + l) * HH;
                float pv = 0.f;
                for (int h = lane; h < HH; h += 32)
                    pv += tanhf(wtwho[(size_t)b * K2H + 512 + h] + yr[h]) * p.V_w[h];
#pragma unroll
                for (int o = 16; o; o >>= 1) pv += __shfl_xor_sync(0xffffffffu, pv, o);
                if (lane == 0) ssc[l] = pv + p.V_b[0];
            }
            __syncthreads();
            float a0 = 0.f, a1 = 0.f;
            for (int l = 0; l < LEN; l++) {
                const float s = ssc[l];
                const float* mr = mid2 + ((size_t)b * LEN + l) * HH;
                a0 += s * mr[tid]; a1 += s * mr[tid + 256];
            }
            DEC16[(size_t)b * 512 + tid]       = __half_as_ushort(__float2half_rn(a0));
            DEC16[(size_t)b * 512 + tid + 256] = __half_as_ushort(__float2half_rn(a1));
        }
        gsync(++ph);
    }
}

__global__ __launch_bounds__(256) void prep_k(
    const float* bihsp, const float* bhhsp, const float* bihtg, const float* bhhtg,
    const float* bihmid, const float* bhhmid, const float* wihtg,
    const float* wtw, const float* whw,
    const float* wisp, const float* whsp, const float* whtg,
    const float* wimd, const float* whmd,
    const float* wiw, const float* wew, const float* vdw, const float* wxw,
    const float* inp)
{
    const int nt = gridDim.x * 256;
    const int gid = blockIdx.x * 256 + threadIdx.x;
    __half* WI16 = (__half*)(g_buf + O_WI16);
    __half* WE16 = (__half*)(g_buf + O_WE16);
    __half* VD16 = (__half*)(g_buf + O_VD16);
    __half* WX16 = (__half*)(g_buf + O_WX16);
    __half* WTWH16 = (__half*)(g_buf + O_WTWH16);
    __half* SPIH = (__half*)(g_buf + O_SPIH);
    __half* SPHH = (__half*)(g_buf + O_SPHH);
    __half* TGX = (__half*)(g_buf + O_TGX);
    __half* TGHH = (__half*)(g_buf + O_TGHH);
    __half* MDIH = (__half*)(g_buf + O_MDIH);
    __half* MDHH = (__half*)(g_buf + O_MDHH);
    __half* INP16 = (__half*)(g_buf + O_INP16);

    for (int i = gid; i < 512*512; i += nt) {
        WI16[i] = __float2half_rn(wiw[i]);
        VD16[i] = __float2half_rn(vdw[i]);
        WX16[i] = __float2half_rn(wxw[i]);
    }
    for (int i = gid; i < 512*1024; i += nt) WE16[i] = __float2half_rn(wew[i]);
    for (int i = gid; i < 1024*1024; i += nt) {
        const int r = i >> 10, c = i & 1023;
        WTWH16[i] = __float2half_rn(r < 512 ? wtw[(size_t)r*1024 + c] : whw[(size_t)(r-512)*1024 + c]);
    }
    for (int i = gid; i < BB*LEN*512; i += nt) INP16[i] = __float2half_rn(inp[i]);
    for (int i = gid; i < H4*512; i += nt) {
        const int rp = i >> 9, kk = i & 511;
        const int h = rp >> 2, gg = rp & 3;
        const size_t src = (size_t)(gg * 512 + h);
        SPIH[i] = __float2half_rn(wisp[src*512 + kk]);
        SPHH[i] = __float2half_rn(whsp[src*512 + kk]);
        TGHH[i] = __float2half_rn(whtg[src*512 + kk]);
        MDIH[i] = __float2half_rn(wimd[src*512 + kk]);
        MDHH[i] = __float2half_rn(whmd[src*512 + kk]);
        TGX[i]  = __float2half_rn(wihtg[src*513 + 1 + kk]);
    }
    for (int i = gid; i < H4; i += nt) {
        const int h = i >> 2, gg = i & 3;
        const int s = gg * 512 + h;
        g_buf[O_BSPI + i]  = bihsp[s] + bhhsp[s];
        g_buf[O_BTGI + i]  = bihtg[s] + bhhtg[s];
        g_buf[O_BMDI + i]  = bihmid[s] + bhhmid[s];
        g_buf[O_WTGCI + i] = wihtg[(size_t)s * 513];
    }
}

__global__ __launch_bounds__(256) void init_k(const float* __restrict__ labp)
{
    const int i = blockIdx.x * 256 + threadIdx.x;
    if (i < NSUB) g_arr[i * 32] = 0u;
    if (i == NSUB) g_master = 0u;
    if (i == NSUB + 1) g_rel = 0u;
    if (i < 4) { g_flagA[i * 32] = 0u; g_flagT[i * 32] = 0u; }
    if (i < BB * K2H) {
        g_buf[O_HT0 + i] = 0.f;
        ((uint16_t*)(g_buf + O_HT16A))[i] = 0;
    }
    if (i < BB * HH) ((uint16_t*)(g_buf + O_DEC16))[i] = 0;
    if (i < BB) g_buf[O_LAB + i] = labp[(size_t)i * LABW + STARTI];
}

extern "C" void kernel_launch(void* const* d_in, const int* in_sizes, int n_in,
                              void* d_out, int out_size)
{
    Params p;
    p.inp   = (const float*)d_in[0];
    p.Wi_b  = (const float*)d_in[15];
    p.Vd_b  = (const float*)d_in[19];
    p.Wx_b  = (const float*)d_in[21];
    p.V_w   = (const float*)d_in[23];
    p.V_b   = (const float*)d_in[24];
    p.reg_w = (const float*)d_in[25];
    p.reg_b = (const float*)d_in[26];
    p.out   = (float*)d_out;

    float* gb = nullptr;
    cudaGetSymbolAddress((void**)&gb, g_buf);
    p.gb = gb;

    cudaFuncSetAttribute(mega, cudaFuncAttributeMaxDynamicSharedMemorySize, SMEMB);

    prep_k<<<2048, 256>>>(
        (const float*)d_in[4], (const float*)d_in[5], (const float*)d_in[8],
        (const float*)d_in[9], (const float*)d_in[12], (const float*)d_in[13],
        (const float*)d_in[6], (const float*)d_in[17], (const float*)d_in[22],
        (const float*)d_in[2], (const float*)d_in[3], (const float*)d_in[7],
        (const float*)d_in[10], (const float*)d_in[11],
        (const float*)d_in[14], (const float*)d_in[16],
        (const float*)d_in[18], (const float*)d_in[20],
        (const float*)d_in[0]);
    init_k<<<(BB * K2H + 255) / 256, 256>>>((const float*)d_in[1]);
    mega<<<NBLK, NTHR, SMEMB>>>(p);
}